// round 17
// baseline (speedup 1.0000x reference)
#include <cuda_runtime.h>
#include <cuda_fp16.h>
#include <math.h>
#include <stdint.h>

#define SQ 4096
#define HIDN 2048
#define NHEAD 16
#define DH 128
#define CB 1024
#define NEGV -1e30f
#define NEGH -5e29f
#define ATT_SCALE 0.08838834764831845f

// ------------- scratch (static __device__ globals; allocation-free) -------------
__device__ float g_q[(size_t)SQ * HIDN];
__device__ float g_lk[(size_t)SQ * HIDN];
__device__ float g_lv[(size_t)SQ * HIDN];
__device__ float g_wlog[SQ];
__device__ float g_entries[(size_t)CB * HIDN];
__device__ float g_ck[CB * DH];
__device__ float g_cv[CB * DH];
__device__ float g_merged[(size_t)SQ * HIDN];
__device__ float g_sc[(size_t)NHEAD * SQ * CB];
__device__ float g_scl[(size_t)NHEAD * 32 * 128 * 256];

// fp16 2-split buffers
__device__ __half g_hid_h[(size_t)SQ * HIDN];
__device__ __half g_hid_l[(size_t)SQ * HIDN];
__device__ __half g_mrg_h[(size_t)SQ * HIDN];
__device__ __half g_mrg_l[(size_t)SQ * HIDN];
__device__ __half g_qh[(size_t)SQ * HIDN];
__device__ __half g_ql[(size_t)SQ * HIDN];
__device__ __half g_lkh[(size_t)SQ * HIDN];
__device__ __half g_lkl[(size_t)SQ * HIDN];
__device__ __half g_lvh[(size_t)SQ * HIDN];
__device__ __half g_lvl[(size_t)SQ * HIDN];
__device__ __half g_ck1[CB * DH];
__device__ __half g_ck2[CB * DH];
__device__ __half g_sph[(size_t)NHEAD * 32 * 128 * 256];
__device__ __half g_spl[(size_t)NHEAD * 32 * 128 * 256];
__device__ __half g_wq1[(size_t)HIDN * HIDN];
__device__ __half g_wq2[(size_t)HIDN * HIDN];
__device__ __half g_wlk_h[(size_t)HIDN * HIDN];
__device__ __half g_wlk_l[(size_t)HIDN * HIDN];
__device__ __half g_wlv_h[(size_t)HIDN * HIDN];
__device__ __half g_wlv_l[(size_t)HIDN * HIDN];
__device__ __half g_wo_h[(size_t)HIDN * HIDN];
__device__ __half g_wo_l[(size_t)HIDN * HIDN];

__device__ __forceinline__ float warp_sum(float v) {
#pragma unroll
    for (int o = 16; o; o >>= 1) v += __shfl_xor_sync(0xffffffffu, v, o);
    return v;
}
__device__ __forceinline__ float warp_max(float v) {
#pragma unroll
    for (int o = 16; o; o >>= 1) v = fmaxf(v, __shfl_xor_sync(0xffffffffu, v, o));
    return v;
}

// ======================= mma.sync helpers (base PTX, sm_80+) =======================
__device__ __forceinline__ uint32_t smem_u32(const void* p) {
    uint32_t a;
    asm("{ .reg .u64 t; cvta.to.shared.u64 t, %1; cvt.u32.u64 %0, t; }" : "=r"(a) : "l"(p));
    return a;
}
__device__ __forceinline__ void ldsm4(uint32_t& r0, uint32_t& r1, uint32_t& r2, uint32_t& r3,
                                      uint32_t addr) {
    asm volatile("ldmatrix.sync.aligned.m8n8.x4.shared.b16 {%0,%1,%2,%3}, [%4];"
                 : "=r"(r0), "=r"(r1), "=r"(r2), "=r"(r3) : "r"(addr));
}
__device__ __forceinline__ void ldsm4t(uint32_t& r0, uint32_t& r1, uint32_t& r2, uint32_t& r3,
                                       uint32_t addr) {
    asm volatile("ldmatrix.sync.aligned.m8n8.x4.trans.shared.b16 {%0,%1,%2,%3}, [%4];"
                 : "=r"(r0), "=r"(r1), "=r"(r2), "=r"(r3) : "r"(addr));
}
__device__ __forceinline__ void mma16816(float* d, const uint32_t* a, const uint32_t* b) {
    asm volatile(
        "mma.sync.aligned.m16n8k16.row.col.f32.f16.f16.f32 "
        "{%0,%1,%2,%3}, {%4,%5,%6,%7}, {%8,%9}, {%0,%1,%2,%3};"
        : "+f"(d[0]), "+f"(d[1]), "+f"(d[2]), "+f"(d[3])
        : "r"(a[0]), "r"(a[1]), "r"(a[2]), "r"(a[3]), "r"(b[0]), "r"(b[1]));
}
// cp.async (Ampere+ base PTX)
__device__ __forceinline__ void cp16(uint32_t dst, const void* src) {
    asm volatile("cp.async.cg.shared.global [%0], [%1], 16;" :: "r"(dst), "l"(src) : "memory");
}
#define CP_COMMIT() asm volatile("cp.async.commit_group;" ::: "memory")
#define CP_WAIT2() asm volatile("cp.async.wait_group 2;" ::: "memory")
#define CP_WAIT1() asm volatile("cp.async.wait_group 1;" ::: "memory")
#define CP_WAIT0() asm volatile("cp.async.wait_group 0;" ::: "memory")

__device__ __forceinline__ uint32_t swz(int row, int c) {
    int slot = (((row & 1) << 2) | c) ^ ((row >> 1) & 7);
    return (uint32_t)(((row >> 1) << 7) + (slot << 4));
}
__device__ __forceinline__ uint32_t vswz(int row, int c) {
    return (uint32_t)((row << 8) + ((c ^ (row & 7)) << 4));
}
// fp16 2-split: x = h + l + e, |e| <= 2^-22 |x|
__device__ __forceinline__ void split2(float x, __half& h, __half& l) {
    h = __float2half_rn(x);
    l = __float2half_rn(__fsub_rn(x, __half2float(h)));
}

extern __shared__ char dynsmem[];

// ------------------------------------------------------------------
// Selection-grade TC GEMM: fp16 2-split, 3 passes (hh,hl,lh) + Kahan
// fold every 2 K-tiles. Block 128x64, 8 warps, K-step 32.
// cp.async 3-stage (3 x 24 KB).
// ------------------------------------------------------------------
__global__ void __launch_bounds__(256)
gemm_tc4k(const __half* __restrict__ A1, const __half* __restrict__ A2,
          const __half* __restrict__ B1, const __half* __restrict__ B2,
          const float* __restrict__ bias, float* __restrict__ C,
          int lda, int ldb, int ldc, int K,
          size_t a_zoff, size_t c_zoff, float scale, int causal)
{
    const int row0 = blockIdx.y << 7;
    const int n0 = blockIdx.x << 6;
    if (causal && n0 >= (row0 >> 2) + 32) return;
    A1 += blockIdx.z * a_zoff; A2 += blockIdx.z * a_zoff;
    C += blockIdx.z * c_zoff;

    const uint32_t sb = smem_u32(dynsmem);
    const int tid = threadIdx.x;
    const int lane = tid & 31, wid = tid >> 5;
    const int wm = wid >> 2, wn = wid & 3;
    const int nt = K >> 5;

    auto stage_load = [&](int t) {
        const int k0 = t << 5;
        const uint32_t st = (uint32_t)(t % 3) * 24576u;
#pragma unroll
        for (int i = 0; i < 2; i++) {
            const int idx = tid + (i << 8);
            const int row = idx >> 2, c = idx & 3;
            const uint32_t off = st + swz(row, c);
            const size_t ga = (size_t)(row0 + row) * lda + k0 + (c << 3);
            cp16(sb + off, A1 + ga);
            cp16(sb + off + 8192, A2 + ga);
        }
        {
            const int row = tid >> 2, c = tid & 3;
            const uint32_t off = st + swz(row, c);
            const size_t gb = (size_t)(n0 + row) * ldb + k0 + (c << 3);
            cp16(sb + off + 16384, B1 + gb);
            cp16(sb + off + 20480, B2 + gb);
        }
        CP_COMMIT();
    };

    float acc[4][2][4], cmp[4][2][4], tmp[4][2][4];
#pragma unroll
    for (int mi = 0; mi < 4; mi++)
#pragma unroll
        for (int ni = 0; ni < 2; ni++)
#pragma unroll
            for (int t = 0; t < 4; t++) {
                acc[mi][ni][t] = 0.f; cmp[mi][ni][t] = 0.f; tmp[mi][ni][t] = 0.f;
            }

    const int lr = lane & 15, lc = lane >> 4;

    stage_load(0);
    if (nt > 1) stage_load(1);
    for (int t = 0; t < nt; t++) {
        if (t + 2 < nt) { stage_load(t + 2); CP_WAIT2(); }
        else if (t + 1 < nt) CP_WAIT1();
        else CP_WAIT0();
        __syncthreads();
        const uint32_t st = (uint32_t)(t % 3) * 24576u;
#pragma unroll
        for (int kh = 0; kh < 2; kh++) {
            const int kc = kh * 2 + lc;
            uint32_t a1[4][4], a2[4][4];
#pragma unroll
            for (int mi = 0; mi < 4; mi++) {
                const int r = wm * 64 + mi * 16 + lr;
                const uint32_t o = st + swz(r, kc);
                ldsm4(a1[mi][0], a1[mi][1], a1[mi][2], a1[mi][3], sb + o);
                ldsm4(a2[mi][0], a2[mi][1], a2[mi][2], a2[mi][3], sb + o + 8192);
            }
            uint32_t b1[2][2], b2[2][2];
            {
                const int r = wn * 16 + lr;
                const uint32_t o = st + swz(r, kc);
                uint32_t r0, r1, r2, r3;
                ldsm4(r0, r1, r2, r3, sb + o + 16384);
                b1[0][0] = r0; b1[1][0] = r1; b1[0][1] = r2; b1[1][1] = r3;
                ldsm4(r0, r1, r2, r3, sb + o + 20480);
                b2[0][0] = r0; b2[1][0] = r1; b2[0][1] = r2; b2[1][1] = r3;
            }
#pragma unroll
            for (int mi = 0; mi < 4; mi++)
#pragma unroll
                for (int ni = 0; ni < 2; ni++) {
                    mma16816(tmp[mi][ni], a1[mi], b1[ni]);
                    mma16816(tmp[mi][ni], a1[mi], b2[ni]);
                    mma16816(tmp[mi][ni], a2[mi], b1[ni]);
                }
        }
        if ((t & 1) || (t == nt - 1)) {
#pragma unroll
            for (int mi = 0; mi < 4; mi++)
#pragma unroll
                for (int ni = 0; ni < 2; ni++)
#pragma unroll
                    for (int q = 0; q < 4; q++) {
                        float y = __fsub_rn(tmp[mi][ni][q], cmp[mi][ni][q]);
                        float t2 = __fadd_rn(acc[mi][ni][q], y);
                        cmp[mi][ni][q] = __fsub_rn(__fsub_rn(t2, acc[mi][ni][q]), y);
                        acc[mi][ni][q] = t2;
                        tmp[mi][ni][q] = 0.f;
                    }
        }
        __syncthreads();
    }
#pragma unroll
    for (int mi = 0; mi < 4; mi++) {
        const int r = row0 + wm * 64 + mi * 16 + (lane >> 2);
#pragma unroll
        for (int ni = 0; ni < 2; ni++) {
            const int cc = n0 + wn * 16 + ni * 8 + ((lane & 3) << 1);
            if (bias) {
                const float b0 = bias[cc], b1v = bias[cc + 1];
                C[(size_t)r * ldc + cc]           = __fadd_rn(acc[mi][ni][0], b0);
                C[(size_t)r * ldc + cc + 1]       = __fadd_rn(acc[mi][ni][1], b1v);
                C[(size_t)(r + 8) * ldc + cc]     = __fadd_rn(acc[mi][ni][2], b0);
                C[(size_t)(r + 8) * ldc + cc + 1] = __fadd_rn(acc[mi][ni][3], b1v);
            } else {
                C[(size_t)r * ldc + cc]           = __fmul_rn(acc[mi][ni][0], scale);
                C[(size_t)r * ldc + cc + 1]       = __fmul_rn(acc[mi][ni][1], scale);
                C[(size_t)(r + 8) * ldc + cc]     = __fmul_rn(acc[mi][ni][2], scale);
                C[(size_t)(r + 8) * ldc + cc + 1] = __fmul_rn(acc[mi][ni][3], scale);
            }
        }
    }
}

// ------------------------------------------------------------------
// Smooth tensor GEMM fp16 3-pass, block 128x128, cp.async 3-stage.
// Optional fp16 2-split outputs fused into epilogue.
// ------------------------------------------------------------------
__global__ void __launch_bounds__(256)
gemm_tc(const __half* __restrict__ Ah, const __half* __restrict__ Al,
        const __half* __restrict__ Bh, const __half* __restrict__ Bl,
        const float* __restrict__ bias, float* __restrict__ C,
        __half* __restrict__ Sh, __half* __restrict__ Sl)
{
    const uint32_t sb = smem_u32(dynsmem);
    const int tid = threadIdx.x;
    const int lane = tid & 31, wid = tid >> 5;
    const int wm = wid >> 2, wn = wid & 3;
    const int row0 = blockIdx.y << 7;
    const int n0 = blockIdx.x << 7;

    auto stage_load = [&](int t) {
        const int k0 = t << 5;
        const uint32_t st = (uint32_t)(t % 3) * 32768u;
#pragma unroll
        for (int i = 0; i < 2; i++) {
            const int idx = tid + (i << 8);
            const int row = idx >> 2, c = idx & 3;
            const uint32_t off = st + swz(row, c);
            const size_t ga = (size_t)(row0 + row) * HIDN + k0 + (c << 3);
            const size_t gb = (size_t)(n0 + row) * HIDN + k0 + (c << 3);
            cp16(sb + off, Ah + ga);
            cp16(sb + off + 8192, Al + ga);
            cp16(sb + off + 16384, Bh + gb);
            cp16(sb + off + 24576, Bl + gb);
        }
        CP_COMMIT();
    };

    float acc[4][4][4];
#pragma unroll
    for (int mi = 0; mi < 4; mi++)
#pragma unroll
        for (int ni = 0; ni < 4; ni++)
#pragma unroll
            for (int t = 0; t < 4; t++) acc[mi][ni][t] = 0.f;

    const int lr = lane & 15, lc = lane >> 4;
    const int nt = HIDN / 32;

    stage_load(0);
    stage_load(1);
    for (int t = 0; t < nt; t++) {
        if (t + 2 < nt) { stage_load(t + 2); CP_WAIT2(); }
        else if (t + 1 < nt) CP_WAIT1();
        else CP_WAIT0();
        __syncthreads();
        const uint32_t st = (uint32_t)(t % 3) * 32768u;
#pragma unroll
        for (int kh = 0; kh < 2; kh++) {
            const int kc = kh * 2 + lc;
            uint32_t a_h[4][4], a_l[4][4];
#pragma unroll
            for (int mi = 0; mi < 4; mi++) {
                const int r = wm * 64 + mi * 16 + lr;
                const uint32_t o = st + swz(r, kc);
                ldsm4(a_h[mi][0], a_h[mi][1], a_h[mi][2], a_h[mi][3], sb + o);
                ldsm4(a_l[mi][0], a_l[mi][1], a_l[mi][2], a_l[mi][3], sb + o + 8192);
            }
            uint32_t b_h[4][2], b_l[4][2];
#pragma unroll
            for (int np = 0; np < 2; np++) {
                const int r = wn * 32 + np * 16 + lr;
                const uint32_t o = st + swz(r, kc);
                uint32_t r0, r1, r2, r3;
                ldsm4(r0, r1, r2, r3, sb + o + 16384);
                b_h[np * 2][0] = r0; b_h[np * 2 + 1][0] = r1;
                b_h[np * 2][1] = r2; b_h[np * 2 + 1][1] = r3;
                ldsm4(r0, r1, r2, r3, sb + o + 24576);
                b_l[np * 2][0] = r0; b_l[np * 2 + 1][0] = r1;
                b_l[np * 2][1] = r2; b_l[np * 2 + 1][1] = r3;
            }
#pragma unroll
            for (int mi = 0; mi < 4; mi++)
#pragma unroll
                for (int ni = 0; ni < 4; ni++) {
                    mma16816(acc[mi][ni], a_h[mi], b_h[ni]);
                    mma16816(acc[mi][ni], a_h[mi], b_l[ni]);
                    mma16816(acc[mi][ni], a_l[mi], b_h[ni]);
                }
        }
        __syncthreads();
    }
#pragma unroll
    for (int mi = 0; mi < 4; mi++) {
        const int r = row0 + wm * 64 + mi * 16 + (lane >> 2);
#pragma unroll
        for (int ni = 0; ni < 4; ni++) {
            const int cc = n0 + wn * 32 + ni * 8 + ((lane & 3) << 1);
            const float b0 = bias[cc], b1 = bias[cc + 1];
            float v00 = __fadd_rn(acc[mi][ni][0], b0);
            float v01 = __fadd_rn(acc[mi][ni][1], b1);
            float v10 = __fadd_rn(acc[mi][ni][2], b0);
            float v11 = __fadd_rn(acc[mi][ni][3], b1);
            size_t o0 = (size_t)r * HIDN + cc;
            size_t o1 = (size_t)(r + 8) * HIDN + cc;
            C[o0] = v00; C[o0 + 1] = v01;
            C[o1] = v10; C[o1 + 1] = v11;
            if (Sh) {
                split2(v00, Sh[o0], Sl[o0]);
                split2(v01, Sh[o0 + 1], Sl[o0 + 1]);
                split2(v10, Sh[o1], Sl[o1]);
                split2(v11, Sh[o1 + 1], Sl[o1 + 1]);
            }
        }
    }
}

// ------------------------------------------------------------------
// Local QK^T: per (h, ch), scores[128 q][256 keys]. fp16 3-pass.
// ------------------------------------------------------------------
__global__ void __launch_bounds__(256)
gemm_tc_qk()
{
    __shared__ char smem[4 * 8192];
    const uint32_t sb = smem_u32(smem);
    const uint32_t SA_H = 0, SA_L = 8192, SB_H = 16384, SB_L = 24576;
    const int tid = threadIdx.x;
    const int lane = tid & 31, wid = tid >> 5;
    const int wm = wid >> 2, wn = wid & 3;
    const int z = blockIdx.y;
    const int h = z >> 5, ch = z & 31;
    const int n0 = blockIdx.x << 7;
    const int b_base = (ch << 7) - 128 + n0;
    const int colA = h * DH;

    float acc[4][4][4];
#pragma unroll
    for (int mi = 0; mi < 4; mi++)
#pragma unroll
        for (int ni = 0; ni < 4; ni++)
#pragma unroll
            for (int t = 0; t < 4; t++) acc[mi][ni][t] = 0.f;

    const int lr = lane & 15, lc = lane >> 4;

    for (int k0 = 0; k0 < DH; k0 += 32) {
#pragma unroll
        for (int i = 0; i < 2; i++) {
            const int idx = tid + (i << 8);
            const int row = idx >> 2, c = idx & 3;
            const uint32_t off = swz(row, c);
            const size_t ga = (size_t)((ch << 7) + row) * HIDN + colA + k0 + (c << 3);
            int br = b_base + row; if (br < 0) br = 0;
            const size_t gb = (size_t)br * HIDN + colA + k0 + (c << 3);
            *(uint4*)(smem + SA_H + off) = *(const uint4*)(g_qh + ga);
            *(uint4*)(smem + SA_L + off) = *(const uint4*)(g_ql + ga);
            *(uint4*)(smem + SB_H + off) = *(const uint4*)(g_lkh + gb);
            *(uint4*)(smem + SB_L + off) = *(const uint4*)(g_lkl + gb);
        }
        __syncthreads();
#pragma unroll
        for (int kh = 0; kh < 2; kh++) {
            const int kc = kh * 2 + lc;
            uint32_t a_h[4][4], a_l[4][4];
#pragma unroll
            for (int mi = 0; mi < 4; mi++) {
                const int r = wm * 64 + mi * 16 + lr;
                const uint32_t o = swz(r, kc);
                ldsm4(a_h[mi][0], a_h[mi][1], a_h[mi][2], a_h[mi][3], sb + SA_H + o);
                ldsm4(a_l[mi][0], a_l[mi][1], a_l[mi][2], a_l[mi][3], sb + SA_L + o);
            }
            uint32_t b_h[4][2], b_l[4][2];
#pragma unroll
            for (int np = 0; np < 2; np++) {
                const int r = wn * 32 + np * 16 + lr;
                const uint32_t o = swz(r, kc);
                uint32_t r0, r1, r2, r3;
                ldsm4(r0, r1, r2, r3, sb + SB_H + o);
                b_h[np * 2][0] = r0; b_h[np * 2 + 1][0] = r1;
                b_h[np * 2][1] = r2; b_h[np * 2 + 1][1] = r3;
                ldsm4(r0, r1, r2, r3, sb + SB_L + o);
                b_l[np * 2][0] = r0; b_l[np * 2 + 1][0] = r1;
                b_l[np * 2][1] = r2; b_l[np * 2 + 1][1] = r3;
            }
#pragma unroll
            for (int mi = 0; mi < 4; mi++)
#pragma unroll
                for (int ni = 0; ni < 4; ni++) {
                    mma16816(acc[mi][ni], a_h[mi], b_h[ni]);
                    mma16816(acc[mi][ni], a_h[mi], b_l[ni]);
                    mma16816(acc[mi][ni], a_l[mi], b_h[ni]);
                }
        }
        __syncthreads();
    }
    float* C = g_scl + (size_t)z * 128 * 256;
#pragma unroll
    for (int mi = 0; mi < 4; mi++) {
        const int r = wm * 64 + mi * 16 + (lane >> 2);
#pragma unroll
        for (int ni = 0; ni < 4; ni++) {
            const int cc = n0 + wn * 32 + ni * 8 + ((lane & 3) << 1);
            C[(size_t)r * 256 + cc]           = __fmul_rn(acc[mi][ni][0], ATT_SCALE);
            C[(size_t)r * 256 + cc + 1]       = __fmul_rn(acc[mi][ni][1], ATT_SCALE);
            C[(size_t)(r + 8) * 256 + cc]     = __fmul_rn(acc[mi][ni][2], ATT_SCALE);
            C[(size_t)(r + 8) * 256 + cc + 1] = __fmul_rn(acc[mi][ni][3], ATT_SCALE);
        }
    }
}

// ------------------------------------------------------------------
// Local PV: ctx = P[128x256]@V[256x128]; merge + emit merged fp16 splits.
// ------------------------------------------------------------------
__global__ void __launch_bounds__(256)
gemm_tc_pv()
{
    __shared__ char smem[4 * 8192];
    const uint32_t sb = smem_u32(smem);
    const uint32_t SP_H = 0, SP_L = 8192, SV_H = 16384, SV_L = 24576;
    const int tid = threadIdx.x;
    const int lane = tid & 31, wid = tid >> 5;
    const int wm = wid >> 2, wn = wid & 3;
    const int z = blockIdx.x;
    const int h = z >> 5, ch = z & 31;
    const int vbase = (ch << 7) - 128;
    const int colV = h * DH;
    const __half* Ph = g_sph + (size_t)z * 128 * 256;
    const __half* Pl = g_spl + (size_t)z * 128 * 256;

    float acc[4][4][4];
#pragma unroll
    for (int mi = 0; mi < 4; mi++)
#pragma unroll
        for (int ni = 0; ni < 4; ni++)
#pragma unroll
            for (int t = 0; t < 4; t++) acc[mi][ni][t] = 0.f;

    const int lr = lane & 15, lc = lane >> 4;

    for (int k0 = 0; k0 < 256; k0 += 32) {
#pragma unroll
        for (int i = 0; i < 2; i++) {
            const int idx = tid + (i << 8);
            const int row = idx >> 2, c = idx & 3;
            const uint32_t off = swz(row, c);
            const size_t gp = (size_t)row * 256 + k0 + (c << 3);
            *(uint4*)(smem + SP_H + off) = *(const uint4*)(Ph + gp);
            *(uint4*)(smem + SP_L + off) = *(const uint4*)(Pl + gp);
        }
#pragma unroll
        for (int i = 0; i < 2; i++) {
            const int idx = tid + (i << 8);
            const int row = idx >> 4, c = idx & 15;
            const uint32_t off = vswz(row, c);
            int vr = vbase + k0 + row; if (vr < 0) vr = 0;
            const size_t gv = (size_t)vr * HIDN + colV + (c << 3);
            *(uint4*)(smem + SV_H + off) = *(const uint4*)(g_lvh + gv);
            *(uint4*)(smem + SV_L + off) = *(const uint4*)(g_lvl + gv);
        }
        __syncthreads();
#pragma unroll
        for (int kh = 0; kh < 2; kh++) {
            const int kc = kh * 2 + lc;
            uint32_t a_h[4][4], a_l[4][4];
#pragma unroll
            for (int mi = 0; mi < 4; mi++) {
                const int r = wm * 64 + mi * 16 + lr;
                const uint32_t o = swz(r, kc);
                ldsm4(a_h[mi][0], a_h[mi][1], a_h[mi][2], a_h[mi][3], sb + SP_H + o);
                ldsm4(a_l[mi][0], a_l[mi][1], a_l[mi][2], a_l[mi][3], sb + SP_L + o);
            }
            uint32_t b_h[4][2], b_l[4][2];
#pragma unroll
            for (int j = 0; j < 2; j++) {
                const int krow = kh * 16 + lr;
                const int dchunk = wn * 4 + j * 2 + lc;
                const uint32_t o = vswz(krow, dchunk);
                uint32_t r0, r1, r2, r3;
                ldsm4t(r0, r1, r2, r3, sb + SV_H + o);
                b_h[j * 2][0] = r0; b_h[j * 2][1] = r1;
                b_h[j * 2 + 1][0] = r2; b_h[j * 2 + 1][1] = r3;
                ldsm4t(r0, r1, r2, r3, sb + SV_L + o);
                b_l[j * 2][0] = r0; b_l[j * 2][1] = r1;
                b_l[j * 2 + 1][0] = r2; b_l[j * 2 + 1][1] = r3;
            }
#pragma unroll
            for (int mi = 0; mi < 4; mi++)
#pragma unroll
                for (int ni = 0; ni < 4; ni++) {
                    mma16816(acc[mi][ni], a_h[mi], b_h[ni]);
                    mma16816(acc[mi][ni], a_h[mi], b_l[ni]);
                    mma16816(acc[mi][ni], a_l[mi], b_h[ni]);
                }
        }
        __syncthreads();
    }
#pragma unroll
    for (int mi = 0; mi < 4; mi++) {
        const int r = (ch << 7) + wm * 64 + mi * 16 + (lane >> 2);
#pragma unroll
        for (int ni = 0; ni < 4; ni++) {
            const int cc = colV + wn * 32 + ni * 8 + ((lane & 3) << 1);
            size_t o0 = (size_t)r * HIDN + cc;
            size_t o1 = (size_t)(r + 8) * HIDN + cc;
            float m00 = __fmul_rn(__fadd_rn(g_merged[o0], acc[mi][ni][0]), 0.5f);
            float m01 = __fmul_rn(__fadd_rn(g_merged[o0 + 1], acc[mi][ni][1]), 0.5f);
            float m10 = __fmul_rn(__fadd_rn(g_merged[o1], acc[mi][ni][2]), 0.5f);
            float m11 = __fmul_rn(__fadd_rn(g_merged[o1 + 1], acc[mi][ni][3]), 0.5f);
            g_merged[o0] = m00; g_merged[o0 + 1] = m01;
            g_merged[o1] = m10; g_merged[o1 + 1] = m11;
            split2(m00, g_mrg_h[o0], g_mrg_l[o0]);
            split2(m01, g_mrg_h[o0 + 1], g_mrg_l[o0 + 1]);
            split2(m10, g_mrg_h[o1], g_mrg_l[o1]);
            split2(m11, g_mrg_h[o1 + 1], g_mrg_l[o1 + 1]);
        }
    }
}

// plain 2-split
__global__ void split2_plain(const float* __restrict__ src,
                             __half* __restrict__ h, __half* __restrict__ l, int n)
{
    int i = blockIdx.x * blockDim.x + threadIdx.x;
    if (i >= n) return;
    split2(src[i], h[i], l[i]);
}

// transpose + 2-split: W [K][N] -> T{h,l} [n][k]
__global__ void tsplit(const float* __restrict__ W,
                       __half* __restrict__ Th, __half* __restrict__ Tl)
{
    __shared__ float tile[32][33];
    const int n0 = blockIdx.x << 5, k0 = blockIdx.y << 5;
    const int tx = threadIdx.x & 31, ty = threadIdx.x >> 5;
#pragma unroll
    for (int i = 0; i < 32; i += 8)
        tile[ty + i][tx] = W[(size_t)(k0 + ty + i) * HIDN + n0 + tx];
    __syncthreads();
#pragma unroll
    for (int i = 0; i < 32; i += 8) {
        float x = tile[tx][ty + i];
        size_t o = (size_t)(n0 + ty + i) * HIDN + k0 + tx;
        split2(x, Th[o], Tl[o]);
    }
}

// ------------------------------------------------------------------
// entries GEMMs (Wk, Wv fused): tile 64x64, chunked-Kahan, 64 CTAs.
// ------------------------------------------------------------------
__global__ __launch_bounds__(256)
void entries_gemm64(const float* __restrict__ Wk, const float* __restrict__ bk,
                    const float* __restrict__ Wv, const float* __restrict__ bv)
{
    const float* W = blockIdx.z ? Wv : Wk;
    const float* bias = blockIdx.z ? bv : bk;
    float* C = blockIdx.z ? g_cv : g_ck;
    const int row0 = blockIdx.y << 6;
    const int col0 = blockIdx.x << 6;

    __shared__ float As[16][64];
    __shared__ float Bs[16][64];
    const int tid = threadIdx.x;
    const int ty = tid >> 4, tx = tid & 15;

    float acc[4][4], cmp[4][4];
#pragma unroll
    for (int i = 0; i < 4; i++)
#pragma unroll
        for (int j = 0; j < 4; j++) { acc[i][j] = 0.f; cmp[i][j] = 0.f; }

    for (int k0 = 0; k0 < HIDN; k0 += 16) {
        {
            int m = tid >> 2, k4 = (tid & 3) << 2;
            float4 v = *(const float4*)(g_entries + (size_t)(row0 + m) * HIDN + k0 + k4);
            As[k4 + 0][m] = v.x; As[k4 + 1][m] = v.y;
            As[k4 + 2][m] = v.z; As[k4 + 3][m] = v.w;
        }
        {
            int kk = tid >> 4, n4 = (tid & 15) << 2;
            *(float4*)&Bs[kk][n4] = *(const float4*)(W + (size_t)(k0 + kk) * DH + col0 + n4);
        }
        __syncthreads();
        float tmp[4][4];
#pragma unroll
        for (int i = 0; i < 4; i++)
#pragma unroll
            for (int j = 0; j < 4; j++) tmp[i][j] = 0.f;
#pragma unroll
        for (int kk = 0; kk < 16; kk++) {
            float ra[4], rb[4];
            *(float4*)&ra[0] = *(const float4*)&As[kk][ty << 2];
            *(float4*)&rb[0] = *(const float4*)&Bs[kk][tx << 2];
#pragma unroll
            for (int i = 0; i < 4; i++)
#pragma unroll
                for (int j = 0; j < 4; j++)
                    tmp[i][j] = __fmaf_rn(ra[i], rb[j], tmp[i][j]);
        }
#pragma unroll
        for (int i = 0; i < 4; i++)
#pragma unroll
            for (int j = 0; j < 4; j++) {
                float y = __fsub_rn(tmp[i][j], cmp[i][j]);
                float t2 = __fadd_rn(acc[i][j], y);
                cmp[i][j] = __fsub_rn(__fsub_rn(t2, acc[i][j]), y);
                acc[i][j] = t2;
            }
        __syncthreads();
    }
#pragma unroll
    for (int i = 0; i < 4; i++) {
        size_t r = row0 + (ty << 2) + i;
#pragma unroll
        for (int j = 0; j < 4; j++) {
            int c = col0 + (tx << 2) + j;
            C[r * DH + c] = __fadd_rn(acc[i][j], bias[c]);
        }
    }
}

// ------------------------------------------------------------------
// rmsnorm + rope with fused fp16 2-split emission.
// ------------------------------------------------------------------
__global__ void norm_rope(int mode, const float* __restrict__ w,
                          __half* __restrict__ s1, __half* __restrict__ s2)
{
    int gw = (blockIdx.x * blockDim.x + threadIdx.x) >> 5;
    int lane = threadIdx.x & 31;
    float* buf; int rows, heads, rstride, pmul, padd;
    if (mode == 0)      { buf = g_q;  rows = SQ; heads = NHEAD; rstride = HIDN; pmul = 1; padd = 0; }
    else if (mode == 1) { buf = g_lk; rows = SQ; heads = NHEAD; rstride = HIDN; pmul = 1; padd = 0; }
    else                { buf = g_ck; rows = CB; heads = 1;     rstride = DH;   pmul = 4; padd = 3; }
    if (gw >= rows * heads) return;
    int row = gw / heads, h = gw - row * heads;
    size_t base = (size_t)row * rstride + h * DH;
    float* p = buf + base;
    float x0 = p[lane], x1 = p[lane + 32], x2 = p[lane + 64], x3 = p[lane + 96];
    float ss = warp_sum(x0 * x0 + x1 * x1 + x2 * x2 + x3 * x3);
    float mean = __fadd_rn(__fmul_rn(ss, 0.0078125f), 1e-6f);
    float rs = __fdiv_rn(1.0f, __fsqrt_rn(mean));
    x0 = __fmul_rn(__fmul_rn(x0, rs), w[lane]);
    x1 = __fmul_rn(__fmul_rn(x1, rs), w[lane + 32]);
    x2 = __fmul_rn(__fmul_rn(x2, rs), w[lane + 64]);
    x3 = __fmul_rn(__fmul_rn(x3, rs), w[lane + 96]);
    float pf = (float)pow(10000.0, (double)lane * (1.0 / 32.0));
    float invf = __fdiv_rn(1.0f, pf);
    float ang = __fmul_rn((float)(row * pmul + padd), invf);
    float c = (float)cos((double)ang);
    float s = (float)sin((double)ang);
    float n0 = __fsub_rn(__fmul_rn(x0, c), __fmul_rn(x1, s));
    float n1 = __fadd_rn(__fmul_rn(x0, s), __fmul_rn(x1, c));
    p[lane] = n0; p[lane + 32] = n1; p[lane + 64] = x2; p[lane + 96] = x3;
    if (s1) {
        float vals[4] = {n0, n1, x2, x3};
        int offs[4] = {lane, lane + 32, lane + 64, lane + 96};
#pragma unroll
        for (int i = 0; i < 4; i++) {
            size_t o = base + offs[i];
            split2(vals[i], s1[o], s2[o]);
        }
    }
}

__global__ void cmp_logits(const float* __restrict__ hidden, const float* __restrict__ Wc,
                           const float* __restrict__ bc)
{
    int gw = (blockIdx.x * blockDim.x + threadIdx.x) >> 5;
    int lane = threadIdx.x & 31;
    if (gw >= SQ) return;
    const float* hr = hidden + (size_t)gw * HIDN;
    float acc = 0.f, cmp = 0.f;
    for (int k = lane; k < HIDN; k += 32) {
        float y = __fmaf_rn(hr[k], Wc[k], -cmp);
        float t = __fadd_rn(acc, y);
        cmp = __fsub_rn(__fsub_rn(t, acc), y);
        acc = t;
    }
    acc = warp_sum(acc);
    if (lane == 0) g_wlog[gw] = __fadd_rn(acc, bc[0]);
}

__global__ void entries_kernel(const float* __restrict__ hidden)
{
    int c = blockIdx.x;
    float w0 = g_wlog[c * 4 + 0], w1 = g_wlog[c * 4 + 1];
    float w2 = g_wlog[c * 4 + 2], w3 = g_wlog[c * 4 + 3];
    float m = fmaxf(fmaxf(w0, w1), fmaxf(w2, w3));
    float e0 = (float)exp((double)__fsub_rn(w0, m));
    float e1 = (float)exp((double)__fsub_rn(w1, m));
    float e2 = (float)exp((double)__fsub_rn(w2, m));
    float e3 = (float)exp((double)__fsub_rn(w3, m));
    float sum = __fadd_rn(__fadd_rn(e0, e1), __fadd_rn(e2, e3));
    e0 = __fdiv_rn(e0, sum); e1 = __fdiv_rn(e1, sum);
    e2 = __fdiv_rn(e2, sum); e3 = __fdiv_rn(e3, sum);
    const float* h0 = hidden + (size_t)c * 4 * HIDN;
    float* dst = g_entries + (size_t)c * HIDN;
    for (int j = threadIdx.x; j < HIDN; j += blockDim.x)
        dst[j] = e0 * h0[j] + e1 * h0[HIDN + j] + e2 * h0[2 * HIDN + j] + e3 * h0[3 * HIDN + j];
}

// ------------------------------------------------------------------
// top-8 over causal prefix + softmax + gather cv; writes 1.0*ctx_sparse
// ------------------------------------------------------------------
__global__ void topk_sparse()
{
    int gw = (blockIdx.x * blockDim.x + threadIdx.x) >> 5;
    int lane = threadIdx.x & 31;
    if (gw >= NHEAD * SQ) return;
    int h = gw >> 12;
    int s = gw & (SQ - 1);
    int nc = (s + 1) >> 2;
    const float* row = g_sc + ((size_t)h * SQ + s) * CB;

    float bv[8]; int bi[8];
#pragma unroll
    for (int i = 0; i < 8; i++) { bv[i] = NEGV; bi[i] = -1; }
    for (int c = lane; c < nc; c += 32) {
        float v = row[c];
        if (v > bv[7]) {
            bv[7] = v; bi[7] = c;
#pragma unroll
            for (int j = 7; j > 0; j--) {
                if (bv[j] > bv[j - 1]) {
                    float tv = bv[j]; bv[j] = bv[j - 1]; bv[j - 1] = tv;
                    int txx = bi[j]; bi[j] = bi[j - 1]; bi[j - 1] = txx;
                }
            }
        }
    }
    int ptr = 0;
    float tvv[8]; int tii[8];
#pragma unroll
    for (int t = 0; t < 8; t++) {
        float m = (ptr < 8) ? bv[ptr] : NEGV;
        int mi = (ptr < 8) ? bi[ptr] : 0x7fffffff;
#pragma unroll
        for (int o = 16; o; o >>= 1) {
            float om = __shfl_xor_sync(0xffffffffu, m, o);
            int oi = __shfl_xor_sync(0xffffffffu, mi, o);
            if (om > m || (om == m && oi < mi)) { m = om; mi = oi; }
        }
        tvv[t] = m; tii[t] = mi;
        if (ptr < 8 && bv[ptr] == m && bi[ptr] == mi) ptr++;
    }
    float m0 = tvv[0];
    float e[8]; float sum = 0.f;
#pragma unroll
    for (int t = 0; t < 8; t++) {
        e[t] = (tvv[t] > NEGH) ? (float)exp((double)__fsub_rn(tvv[t], m0)) : 0.f;
        sum += e[t];
    }
    float den = fmaxf(sum, 1e-9f);
    float c0 = 0.f, c1 = 0.f, c2 = 0.f, c3 = 0.f;
#pragma unroll
    for (int t = 0; t < 8; t++) {
        float wgt = __fdiv_rn(e[t], den);
        if (wgt > 0.f) {
            const float* vr = g_cv + (size_t)tii[t] * DH;
            c0 += wgt * vr[lane];      c1 += wgt * vr[lane + 32];
            c2 += wgt * vr[lane + 64]; c3 += wgt * vr[lane + 96];
        }
    }
    float* dst = g_merged + (size_t)s * HIDN + h * DH;
    dst[lane] = c0;      dst[lane + 32] = c1;
    dst[lane + 64] = c2; dst[lane + 96] = c3;
}

// masked softmax over 256 local keys; writes fp16 split probs
__global__ void local_softmax()
{
    int gw = (blockIdx.x * blockDim.x + threadIdx.x) >> 5;
    int lane = threadIdx.x & 31;
    if (gw >= NHEAD * 32 * 128) return;
    int qi = gw & 127;
    int ch = (gw >> 7) & 31;
    const float* rowp = g_scl + (size_t)gw * 256;
    __half* oh = g_sph + (size_t)gw * 256;
    __half* ol = g_spl + (size_t)gw * 256;
    int lo = (ch == 0) ? 128 : qi;
    int hi = qi + 128;
    float v[8];
    float m = NEGV;
#pragma unroll
    for (int t = 0; t < 8; t++) {
        int j = lane + (t << 5);
        bool ok = (j >= lo) && (j <= hi);
        v[t] = ok ? rowp[j] : NEGV;
        m = fmaxf(m, v[t]);
    }
    m = warp_max(m);
    float e[8]; float sum = 0.f;
#pragma unroll
    for (int t = 0; t < 8; t++) {
        int j = lane + (t << 5);
        bool ok = (j >= lo) && (j <= hi);
        e[t] = ok ? (float)exp((double)__fsub_rn(v[t], m)) : 0.f;
        sum += e[t];
    }
    sum = warp_sum(sum);
#pragma unroll
    for (int t = 0; t < 8; t++) {
        float p = __fdiv_rn(e[t], sum);
        split2(p, oh[lane + (t << 5)], ol[lane + (t << 5)]);
    }
}

// ------------------------------------------------------------------
extern "C" void kernel_launch(void* const* d_in, const int* in_sizes, int n_in,
                              void* d_out, int out_size)
{
    const float* hidden = (const float*)d_in[0];
    const float* Wq   = (const float*)d_in[1];
    const float* bq   = (const float*)d_in[2];
    const float* Wcmp = (const float*)d_in[3];
    const float* bcmp = (const float*)d_in[4];
    const float* Wk   = (const float*)d_in[5];
    const float* bk   = (const float*)d_in[6];
    const float* Wv   = (const float*)d_in[7];
    const float* bvv  = (const float*)d_in[8];
    const float* Wlk  = (const float*)d_in[9];
    const float* blkb = (const float*)d_in[10];
    const float* Wlv  = (const float*)d_in[11];
    const float* blvb = (const float*)d_in[12];
    const float* qnw  = (const float*)d_in[13];
    const float* knw  = (const float*)d_in[14];
    const float* Wo   = (const float*)d_in[15];
    const float* bo   = (const float*)d_in[16];
    float* out = (float*)d_out;

    static __half *hid_h = nullptr, *hid_l, *mrg_h, *mrg_l,
                  *wlk_h, *wlk_l, *wlv_h, *wlv_l, *wo_h, *wo_l,
                  *qh, *ql, *lkh, *lkl, *lvh, *lvl,
                  *wq1, *wq2, *ck1, *ck2;
    static float *p_q = nullptr, *p_lk, *p_lv, *p_merged, *p_ck, *p_sc;
    static cudaStream_t s1 = nullptr, s2 = nullptr;
    static cudaEvent_t evRoot, evHid, evQ, evCk, evS1, evS2;
    static bool init_done = false;
    if (!init_done) {
        cudaFuncSetAttribute(gemm_tc, cudaFuncAttributeMaxDynamicSharedMemorySize, 98304);
        cudaFuncSetAttribute(gemm_tc4k, cudaFuncAttributeMaxDynamicSharedMemorySize, 73728);
        cudaStreamCreateWithFlags(&s1, cudaStreamNonBlocking);
        cudaStreamCreateWithFlags(&s2, cudaStreamNonBlocking);
        cudaEventCreateWithFlags(&evRoot, cudaEventDisableTiming);
        cudaEventCreateWithFlags(&evHid, cudaEventDisableTiming);
        cudaEventCreateWithFlags(&evQ,   cudaEventDisableTiming);
        cudaEventCreateWithFlags(&evCk,  cudaEventDisableTiming);
        cudaEventCreateWithFlags(&evS1,  cudaEventDisableTiming);
        cudaEventCreateWithFlags(&evS2,  cudaEventDisableTiming);
        cudaGetSymbolAddress((void**)&hid_h, g_hid_h);
        cudaGetSymbolAddress((void**)&hid_l, g_hid_l);
        cudaGetSymbolAddress((void**)&mrg_h, g_mrg_h);
        cudaGetSymbolAddress((void**)&mrg_l, g_mrg_l);
        cudaGetSymbolAddress((void**)&wlk_h, g_wlk_h);
        cudaGetSymbolAddress((void**)&wlk_l, g_wlk_l);
        cudaGetSymbolAddress((void**)&wlv_h, g_wlv_h);
        cudaGetSymbolAddress((void**)&wlv_l, g_wlv_l);
        cudaGetSymbolAddress((void**)&wo_h, g_wo_h);
        cudaGetSymbolAddress((void**)&wo_l, g_wo_l);
        cudaGetSymbolAddress((void**)&qh, g_qh);
        cudaGetSymbolAddress((void**)&ql, g_ql);
        cudaGetSymbolAddress((void**)&lkh, g_lkh);
        cudaGetSymbolAddress((void**)&lkl, g_lkl);
        cudaGetSymbolAddress((void**)&lvh, g_lvh);
        cudaGetSymbolAddress((void**)&lvl, g_lvl);
        cudaGetSymbolAddress((void**)&wq1, g_wq1);
        cudaGetSymbolAddress((void**)&wq2, g_wq2);
        cudaGetSymbolAddress((void**)&ck1, g_ck1);
        cudaGetSymbolAddress((void**)&ck2, g_ck2);
        cudaGetSymbolAddress((void**)&p_q, g_q);
        cudaGetSymbolAddress((void**)&p_lk, g_lk);
        cudaGetSymbolAddress((void**)&p_lv, g_lv);
        cudaGetSymbolAddress((void**)&p_merged, g_merged);
        cudaGetSymbolAddress((void**)&p_ck, g_ck);
        cudaGetSymbolAddress((void**)&p_sc, g_sc);
        init_done = true;
    }

    const int NELT = SQ * HIDN;

    // ---------- fork point: side streams must first wait on an event recorded
    // in the capturing stream (stream 0), otherwise capture is invalidated ----
    cudaEventRecord(evRoot, 0);
    cudaStreamWaitEvent(s1, evRoot, 0);
    cudaStreamWaitEvent(s2, evRoot, 0);

    // ---------- main stream (0): hidden split -> Wq chain ----------
    split2_plain<<<(NELT + 255) / 256, 256>>>(hidden, hid_h, hid_l, NELT);
    cudaEventRecord(evHid, 0);

    // ---------- s1: cmp/entries chain + Wlv + Wo tsplit ----------
    cmp_logits<<<SQ / 8, 256, 0, s1>>>(hidden, Wcmp, bcmp);
    entries_kernel<<<CB, 256, 0, s1>>>(hidden);
    entries_gemm64<<<dim3(2, 16, 2), 256, 0, s1>>>(Wk, bk, Wv, bvv);
    norm_rope<<<CB / 8, 256, 0, s1>>>(2, knw, ck1, ck2);
    cudaEventRecord(evCk, s1);
    tsplit<<<dim3(64, 64), 256, 0, s1>>>(Wlv, wlv_h, wlv_l);
    cudaStreamWaitEvent(s1, evHid, 0);
    gemm_tc<<<dim3(HIDN / 128, SQ / 128), 256, 98304, s1>>>(hid_h, hid_l, wlv_h, wlv_l,
                                                            blvb, p_lv, lvh, lvl);
    tsplit<<<dim3(64, 64), 256, 0, s1>>>(Wo, wo_h, wo_l);
    cudaEventRecord(evS1, s1);

    // ---------- s2: Wlk chain -> local QK -> softmax ----------
    tsplit<<<dim3(64, 64), 256, 0, s2>>>(Wlk, wlk_h, wlk_l);
    cudaStreamWaitEvent(s2, evHid, 0);
    gemm_tc<<<dim3(HIDN / 128, SQ / 128), 256, 98304, s2>>>(hid_h, hid_l, wlk_h, wlk_l,
                                                            blkb, p_lk, nullptr, nullptr);
    norm_rope<<<(SQ * NHEAD) / 8, 256, 0, s2>>>(1, knw, lkh, lkl);

    // ---------- main: Wq chain ----------
    tsplit<<<dim3(64, 64), 256>>>(Wq, wq1, wq2);
    gemm_tc4k<<<dim3(HIDN / 64, SQ / 128, 1), 256, 73728>>>(
        hid_h, hid_l, wq1, wq2, bq, p_q,
        HIDN, HIDN, HIDN, HIDN, 0, 0, 1.0f, 0);
    norm_rope<<<(SQ * NHEAD) / 8, 256>>>(0, qnw, qh, ql);
    cudaEventRecord(evQ, 0);

    // s2 continues: local QK needs q splits
    cudaStreamWaitEvent(s2, evQ, 0);
    gemm_tc_qk<<<dim3(2, NHEAD * 32), 256, 0, s2>>>();
    local_softmax<<<(NHEAD * 32 * 128) / 8, 256, 0, s2>>>();
    cudaEventRecord(evS2, s2);

    // main: compressed scores (needs ck splits) + topk
    cudaStreamWaitEvent(0, evCk, 0);
    gemm_tc4k<<<dim3(CB / 64, SQ / 128, NHEAD), 256, 73728>>>(
        qh, ql, ck1, ck2, nullptr, p_sc,
        HIDN, DH, CB, DH, (size_t)DH, (size_t)SQ * CB, ATT_SCALE, 1);
    topk_sparse<<<(NHEAD * SQ) / 8, 256>>>();

    // join: pv needs softmax probs (s2), lv splits (s1), merged (main)
    cudaStreamWaitEvent(0, evS2, 0);
    cudaStreamWaitEvent(0, evS1, 0);
    gemm_tc_pv<<<NHEAD * 32, 256>>>();

    // output projection (wo splits covered by evS1)
    gemm_tc<<<dim3(HIDN / 128, SQ / 128), 256, 98304>>>(mrg_h, mrg_l, wo_h, wo_l,
                                                        bo, out, nullptr, nullptr);
}